// round 11
// baseline (speedup 1.0000x reference)
#include <cuda_runtime.h>
#include <cuda_bf16.h>
#include <cstdint>

#define NN 4096
#define FF 512
#define DD 128
#define HH 8
#define KC 64
#define NCHUNK (NN / KC)

// ---------------- scratch (static device globals; no allocs) ----------------
__device__ __nv_bfloat16 g_featb[NN * FF];          // 4 MB
__device__ __nv_bfloat16 g_Wb[HH * FF * DD];        // 1 MB
__device__ __nv_bfloat16 g_Bp[HH * NN * 136];       // 8.9 MB: [h][j][0:128]=e2p*Wh, [128]=e2p, [129:136]=0
__device__ float g_ratio[HH * NN];                  // r_i = exp(-0.8 s1)
__device__ __nv_bfloat16 g_e2rb[HH * NN];           // e2r_j = exp(-0.8 s2), bf16
__device__ unsigned g_adjbits[NN * (NN / 32)];      // 2 MB
__device__ float g_haccum[HH * NN * DD];            // 16 MB per-head elu(h')

// ---------------- helpers ----------------
__device__ __forceinline__ unsigned pack_bf16x2(float lo, float hi) {
    unsigned r;
    asm("cvt.rn.bf16x2.f32 %0, %1, %2;" : "=r"(r) : "f"(hi), "f"(lo));
    return r;
}
__device__ __forceinline__ unsigned smem_u32(const void* p) {
    return (unsigned)__cvta_generic_to_shared(p);
}
__device__ __forceinline__ unsigned SWZ(unsigned off) {        // SW128 swizzle
    return off ^ ((off >> 3) & 0x70);
}
__device__ __forceinline__ void ldsm_x4(unsigned addr, unsigned& r0, unsigned& r1,
                                        unsigned& r2, unsigned& r3) {
    asm volatile("ldmatrix.sync.aligned.m8n8.x4.shared.b16 {%0,%1,%2,%3}, [%4];"
                 : "=r"(r0), "=r"(r1), "=r"(r2), "=r"(r3) : "r"(addr));
}
__device__ __forceinline__ void ldsm_x4_t(unsigned addr, unsigned& r0, unsigned& r1,
                                          unsigned& r2, unsigned& r3) {
    asm volatile("ldmatrix.sync.aligned.m8n8.x4.trans.shared.b16 {%0,%1,%2,%3}, [%4];"
                 : "=r"(r0), "=r"(r1), "=r"(r2), "=r"(r3) : "r"(addr));
}
__device__ __forceinline__ void ldsm_x2_t(unsigned addr, unsigned& r0, unsigned& r1) {
    asm volatile("ldmatrix.sync.aligned.m8n8.x2.trans.shared.b16 {%0,%1}, [%2];"
                 : "=r"(r0), "=r"(r1) : "r"(addr));
}
__device__ __forceinline__ void mma_bf16(float* c, unsigned a0, unsigned a1, unsigned a2,
                                         unsigned a3, unsigned b0, unsigned b1) {
    asm volatile(
        "mma.sync.aligned.m16n8k16.row.col.f32.bf16.bf16.f32 "
        "{%0,%1,%2,%3}, {%4,%5,%6,%7}, {%8,%9}, {%0,%1,%2,%3};"
        : "+f"(c[0]), "+f"(c[1]), "+f"(c[2]), "+f"(c[3])
        : "r"(a0), "r"(a1), "r"(a2), "r"(a3), "r"(b0), "r"(b1));
}
#define CP_ASYNC16(dst, src) \
    asm volatile("cp.async.cg.shared.global [%0], [%1], 16;" :: "r"(dst), "l"(src))
#define CP_COMMIT asm volatile("cp.async.commit_group;")
#define CP_WAIT0 asm volatile("cp.async.wait_group 0;")

#define BAR_SYNC(id, cnt) \
    asm volatile("bar.sync %0, %1;" :: "r"(id), "r"(cnt) : "memory")
#define BAR_ARRIVE(id, cnt) \
    asm volatile("bar.arrive %0, %1;" :: "r"(id), "r"(cnt) : "memory")

__device__ __forceinline__ void sts128(unsigned addr, unsigned a, unsigned b,
                                       unsigned c, unsigned d) {
    asm volatile("st.shared.v4.b32 [%0], {%1,%2,%3,%4};"
                 :: "r"(addr), "r"(a), "r"(b), "r"(c), "r"(d));
}
__device__ __forceinline__ float elu1(float v) {
    return (v > 0.0f) ? v : (__expf(v) - 1.0f);
}
__device__ __forceinline__ unsigned hmul2bf(unsigned a, unsigned b) {
    unsigned d;
    asm("mul.bf16x2 %0, %1, %2;" : "=r"(d) : "r"(a), "r"(b));
    return d;
}
__device__ __forceinline__ unsigned hmax2one(unsigned a) {
    unsigned d;
    asm("max.bf16x2 %0, %1, %2;" : "=r"(d) : "r"(a), "r"(0x3f803f80u));
    return d;
}
__device__ __forceinline__ unsigned mpair(unsigned mb, int s) {
    return (((mb >> s) & 1u) ? 0x0000FFFFu : 0u) | (((mb >> s) & 2u) ? 0xFFFF0000u : 0u);
}

// ---------------- kernel 1: convert feature/W to bf16 ----------------
__global__ void prep_kernel(const float* __restrict__ feature, const float* __restrict__ W) {
    int i = blockIdx.x * 256 + threadIdx.x;          // 524288 threads
    #pragma unroll
    for (int r = 0; r < 4; r++) {
        int k = i + r * 524288;                       // NN*FF
        g_featb[k] = __float2bfloat16(feature[k]);
    }
    g_Wb[i] = __float2bfloat16(W[i]);                // HH*FF*DD
}

// ---------------- kernel 2: adjacency -> bitmask ----------------
__global__ void pack_adj_kernel(const int* __restrict__ adj) {
    int gid = blockIdx.x * 256 + threadIdx.x;
    int w = gid >> 5;
    int lane = gid & 31;
    unsigned mask = __ballot_sync(0xffffffffu, adj[(size_t)w * 32 + lane] > 0);
    if (lane == 0) g_adjbits[w] = mask;
}

// ---------------- kernel 3: Wh = feature @ W[h]; epilogue emits e2p*Wh, ratio, e2r ----------------
__global__ void __launch_bounds__(256, 2) proj_kernel(const float* __restrict__ a1,
                                                      const float* __restrict__ a2) {
    __shared__ __nv_bfloat16 sA[128][72];
    __shared__ __nv_bfloat16 sB[64][136];
    __shared__ float sA1[128], sA2[128];

    int h = blockIdx.y;
    int rowbase = blockIdx.x * 128;
    int t = threadIdx.x;
    int warp = t >> 5, lane = t & 31;
    int g = lane >> 2, tid4 = lane & 3;
    int m0 = warp * 16;
    int lr = (lane & 7) + ((lane & 8) ? 8 : 0);
    int lc = (lane & 16) ? 8 : 0;

    if (t < 128) sA1[t] = a1[h * DD + t];
    else sA2[t - 128] = a2[h * DD + (t - 128)];

    float acc[16][4];
    #pragma unroll
    for (int i = 0; i < 16; i++)
        #pragma unroll
        for (int j = 0; j < 4; j++) acc[i][j] = 0.0f;

    for (int kc = 0; kc < FF; kc += 64) {
        __syncthreads();
        const uint4* gA = (const uint4*)(g_featb + (size_t)rowbase * FF + kc);
        #pragma unroll
        for (int r = 0; r < 4; r++) {
            int li = r * 256 + t;
            int row = li >> 3, q = li & 7;
            *(uint4*)&sA[row][q * 8] = gA[row * (FF / 8) + q];
        }
        const uint4* gB = (const uint4*)(g_Wb + ((size_t)h * FF + kc) * DD);
        #pragma unroll
        for (int r = 0; r < 4; r++) {
            int li = r * 256 + t;
            int row = li >> 4, q = li & 15;
            *(uint4*)&sB[row][q * 8] = gB[row * 16 + q];
        }
        __syncthreads();

        #pragma unroll
        for (int kk = 0; kk < 64; kk += 16) {
            unsigned a0, a1r, a2r, a3;
            ldsm_x4(smem_u32(&sA[m0 + lr][kk + lc]), a0, a1r, a2r, a3);
            #pragma unroll
            for (int nb = 0; nb < 8; nb++) {
                unsigned b0, b1, b2, b3;
                ldsm_x4_t(smem_u32(&sB[kk + lr][nb * 16 + lc]), b0, b1, b2, b3);
                mma_bf16(acc[2 * nb], a0, a1r, a2r, a3, b0, b1);
                mma_bf16(acc[2 * nb + 1], a0, a1r, a2r, a3, b2, b3);
            }
        }
    }

    int row_lo = rowbase + m0 + g;
    int row_hi = row_lo + 8;

    // s1/s2 dot products first (need unscaled accs)
    float d1lo = 0, d2lo = 0, d1hi = 0, d2hi = 0;
    #pragma unroll
    for (int i = 0; i < 16; i++) {
        int col = i * 8 + 2 * tid4;
        float v1a = sA1[col], v1b = sA1[col + 1];
        float v2a = sA2[col], v2b = sA2[col + 1];
        d1lo += acc[i][0] * v1a + acc[i][1] * v1b;
        d1hi += acc[i][2] * v1a + acc[i][3] * v1b;
        d2lo += acc[i][0] * v2a + acc[i][1] * v2b;
        d2hi += acc[i][2] * v2a + acc[i][3] * v2b;
    }
    #pragma unroll
    for (int o = 1; o <= 2; o <<= 1) {
        d1lo += __shfl_xor_sync(0xffffffffu, d1lo, o);
        d1hi += __shfl_xor_sync(0xffffffffu, d1hi, o);
        d2lo += __shfl_xor_sync(0xffffffffu, d2lo, o);
        d2hi += __shfl_xor_sync(0xffffffffu, d2hi, o);
    }
    float e2p_lo = __expf(d2lo), e2p_hi = __expf(d2hi);

    // write B' = e2p * Wh (bf16, stride 136)
    __nv_bfloat16* outlo = g_Bp + ((size_t)h * NN + row_lo) * 136;
    __nv_bfloat16* outhi = g_Bp + ((size_t)h * NN + row_hi) * 136;
    #pragma unroll
    for (int i = 0; i < 16; i++) {
        int col = i * 8 + 2 * tid4;
        *(unsigned*)(outlo + col) = pack_bf16x2(acc[i][0] * e2p_lo, acc[i][1] * e2p_lo);
        *(unsigned*)(outhi + col) = pack_bf16x2(acc[i][2] * e2p_hi, acc[i][3] * e2p_hi);
    }
    if (tid4 == 0) {
        // cols 128..135: [e2p, 0, 0, 0, 0, 0, 0, 0]
        *(uint4*)(outlo + 128) = make_uint4(pack_bf16x2(e2p_lo, 0.0f), 0u, 0u, 0u);
        *(uint4*)(outhi + 128) = make_uint4(pack_bf16x2(e2p_hi, 0.0f), 0u, 0u, 0u);
        int ilo = h * NN + row_lo, ihi = h * NN + row_hi;
        g_ratio[ilo] = __expf(-0.8f * d1lo);
        g_ratio[ihi] = __expf(-0.8f * d1hi);
        g_e2rb[ilo] = __float2bfloat16(__expf(-0.8f * d2lo));
        g_e2rb[ihi] = __float2bfloat16(__expf(-0.8f * d2hi));
    }
}

// ---------------- kernel 4: warp-specialized masked-softmax aggregation ----------------
// 640 threads: warps 0-15 = consumers (pure ldsm+mma, 256x128 output, tile 32x64),
// warps 16-19 = producers (score-gen + cp.async B/Z). Named-barrier handshake,
// double-buffered P (2x32K) and B (2x16K). grid (16, 8) = 128 CTAs, 1 CTA/SM.
#define OFF_P   0        // 2 x 32768
#define OFF_B   65536    // 2 x 16384
#define OFF_ZC  98304    // 2 x 1024
#define OFF_ZP  100352   // 1024 (1/Z publish)
#define OFF_E2R 101376   // 8192
#define ATTN_SMEM_BYTES (109568 + 1024)

#define BARF0 1
#define BARF1 2
#define BARE0 3
#define BARE1 4
#define BARC  5

__global__ void __launch_bounds__(640, 1) attn_kernel() {
    extern __shared__ char smraw[];
    unsigned sb = (smem_u32(smraw) + 1023u) & ~1023u;
    unsigned sP = sb + OFF_P;
    unsigned sBB = sb + OFF_B;
    unsigned sZ = sb + OFF_ZC;
    unsigned sZP = sb + OFF_ZP;
    unsigned sE = sb + OFF_E2R;

    int t = threadIdx.x;
    int lane = t & 31, w = t >> 5;
    int h = blockIdx.y;
    int rowbase = blockIdx.x * 256;
    const char* bsrc = (const char*)(g_Bp + (size_t)h * NN * 136);

    if (w >= 16) {
        // ======================= PRODUCER (warps 16-19) =======================
        int pt = t - 512;                       // 0..127
        int lp0 = pt * 2, lp1 = lp0 + 1;        // local P rows
        int pr0 = rowbase + lp0, pr1 = rowbase + lp1;

        // stage e2r table (8 KB)
        const __nv_bfloat16* e2rsrc = g_e2rb + (size_t)h * NN;
        #pragma unroll
        for (int j = 0; j < 4; j++)
            CP_ASYNC16(sE + pt * 64 + j * 16, e2rsrc + pt * 32 + j * 8);
        CP_COMMIT;

        float r0f = g_ratio[h * NN + pr0];
        float r1f = g_ratio[h * NN + pr1];
        unsigned rr0 = pack_bf16x2(r0f, r0f);
        unsigned rr1 = pack_bf16x2(r1f, r1f);
        const uint2* adj0 = (const uint2*)&g_adjbits[(size_t)pr0 * (NN / 32)];
        const uint2* adj1 = (const uint2*)&g_adjbits[(size_t)pr1 * (NN / 32)];

        CP_WAIT0;            // e2r resident (only our own group)

        for (int i = 0; i < NCHUNK; i++) {
            int slot = i & 1;
            int kc = i * KC;
            if (i >= 2) BAR_SYNC(BARE0 + slot, 640);

            // issue B(i) + Z(i)
            const char* src = bsrc + (size_t)kc * 272;
            unsigned db = sBB + slot * 16384;
            #pragma unroll
            for (int r = 0; r < 8; r++) {
                int li = r * 128 + pt;
                int row = li >> 4, q = li & 15;
                CP_ASYNC16(db + (q >> 3) * 8192 + SWZ(row * 128 + (q & 7) * 16),
                           src + row * 272 + q * 16);
            }
            if (pt < 64) CP_ASYNC16(sZ + slot * 1024 + pt * 16, src + pt * 272 + 256);
            CP_COMMIT;

            // score-gen P(i): 2 rows x 64 cols
            uint2 wa = adj0[i], wb = adj1[i];
            unsigned pb = sP + slot * 32768;
            #pragma unroll
            for (int gi = 0; gi < 8; gi++) {
                unsigned ex, ey, ez, ew;
                asm volatile("ld.shared.v4.b32 {%0,%1,%2,%3}, [%4];"
                             : "=r"(ex), "=r"(ey), "=r"(ez), "=r"(ew)
                             : "r"(sE + (kc + gi * 8) * 2));
                unsigned m0b = (gi < 4) ? (wa.x >> (gi * 8)) : (wa.y >> ((gi - 4) * 8));
                unsigned m1b = (gi < 4) ? (wb.x >> (gi * 8)) : (wb.y >> ((gi - 4) * 8));
                sts128(pb + SWZ(lp0 * 128 + gi * 16),
                       hmax2one(hmul2bf(rr0, ex)) & mpair(m0b, 0),
                       hmax2one(hmul2bf(rr0, ey)) & mpair(m0b, 2),
                       hmax2one(hmul2bf(rr0, ez)) & mpair(m0b, 4),
                       hmax2one(hmul2bf(rr0, ew)) & mpair(m0b, 6));
                sts128(pb + SWZ(lp1 * 128 + gi * 16),
                       hmax2one(hmul2bf(rr1, ex)) & mpair(m1b, 0),
                       hmax2one(hmul2bf(rr1, ey)) & mpair(m1b, 2),
                       hmax2one(hmul2bf(rr1, ez)) & mpair(m1b, 4),
                       hmax2one(hmul2bf(rr1, ew)) & mpair(m1b, 6));
            }
            CP_WAIT0;                         // B(i)/Z(i) landed
            BAR_ARRIVE(BARF0 + slot, 640);    // publish P(i)+B(i)
        }
        return;                                // producers exit
    }

    // ======================= CONSUMER (warps 0-15) =======================
    int g = lane >> 2, tid4 = lane & 3;
    int mw = w & 7, nw = w >> 3;
    int m0 = mw * 32, n0 = nw * 64;
    int lr = (lane & 7) + ((lane & 8) ? 8 : 0);
    int lc = (lane & 16) ? 8 : 0;

    float acc[16][4];
    #pragma unroll
    for (int i = 0; i < 16; i++)
        #pragma unroll
        for (int j = 0; j < 4; j++) acc[i][j] = 0.0f;
    float zA[4] = {0, 0, 0, 0}, zB[4] = {0, 0, 0, 0};

    for (int i = 0; i < NCHUNK; i++) {
        int slot = i & 1;
        BAR_SYNC(BARF0 + slot, 640);          // P(i)+B(i) ready

        unsigned pb = sP + slot * 32768;
        unsigned bh = sBB + slot * 16384 + nw * 8192;
        unsigned zb = sZ + slot * 1024;
        #pragma unroll
        for (int kk = 0; kk < 4; kk++) {
            unsigned A00, A01, A02, A03, A10, A11, A12, A13;
            ldsm_x4(pb + SWZ((m0 + lr) * 128 + (kk * 16 + lc) * 2), A00, A01, A02, A03);
            ldsm_x4(pb + SWZ((m0 + 16 + lr) * 128 + (kk * 16 + lc) * 2), A10, A11, A12, A13);
            #pragma unroll
            for (int nb4 = 0; nb4 < 4; nb4++) {
                unsigned b0, b1, b2, b3;
                ldsm_x4_t(bh + SWZ((kk * 16 + lr) * 128 + (nb4 * 16 + lc) * 2),
                          b0, b1, b2, b3);
                mma_bf16(acc[2 * nb4],     A00, A01, A02, A03, b0, b1);
                mma_bf16(acc[2 * nb4 + 1], A00, A01, A02, A03, b2, b3);
                mma_bf16(acc[8 + 2 * nb4],     A10, A11, A12, A13, b0, b1);
                mma_bf16(acc[8 + 2 * nb4 + 1], A10, A11, A12, A13, b2, b3);
            }
            if (nw == 0) {                    // Z dedup: one N-group only
                unsigned zb0, zb1;
                ldsm_x2_t(zb + (kk * 16 + (lane & 15)) * 16, zb0, zb1);
                mma_bf16(zA, A00, A01, A02, A03, zb0, zb1);
                mma_bf16(zB, A10, A11, A12, A13, zb0, zb1);
            }
        }
        BAR_ARRIVE(BARE0 + slot, 640);        // buffers free (data already in regs)
    }

    // publish 1/Z (consumer-only barrier)
    if (nw == 0 && tid4 == 0) {
        asm volatile("st.shared.f32 [%0], %1;" :: "r"(sZP + (m0 + g) * 4),      "f"(1.0f / zA[0]));
        asm volatile("st.shared.f32 [%0], %1;" :: "r"(sZP + (m0 + g + 8) * 4),  "f"(1.0f / zA[2]));
        asm volatile("st.shared.f32 [%0], %1;" :: "r"(sZP + (m0 + g + 16) * 4), "f"(1.0f / zB[0]));
        asm volatile("st.shared.f32 [%0], %1;" :: "r"(sZP + (m0 + g + 24) * 4), "f"(1.0f / zB[2]));
    }
    BAR_SYNC(BARC, 512);
    float i0, i1, i2, i3;
    asm volatile("ld.shared.f32 %0, [%1];" : "=f"(i0) : "r"(sZP + (m0 + g) * 4));
    asm volatile("ld.shared.f32 %0, [%1];" : "=f"(i1) : "r"(sZP + (m0 + g + 8) * 4));
    asm volatile("ld.shared.f32 %0, [%1];" : "=f"(i2) : "r"(sZP + (m0 + g + 16) * 4));
    asm volatile("ld.shared.f32 %0, [%1];" : "=f"(i3) : "r"(sZP + (m0 + g + 24) * 4));

    int r0 = rowbase + m0 + g;
    float* o0 = g_haccum + ((size_t)h * NN + r0) * DD;
    float* o1 = o0 + 8 * DD;
    float* o2 = o0 + 16 * DD;
    float* o3 = o0 + 24 * DD;
    #pragma unroll
    for (int nb = 0; nb < 8; nb++) {
        int col = n0 + nb * 8 + 2 * tid4;
        float2 v0 = make_float2(elu1(acc[nb][0] * i0), elu1(acc[nb][1] * i0));
        float2 v1 = make_float2(elu1(acc[nb][2] * i1), elu1(acc[nb][3] * i1));
        float2 v2 = make_float2(elu1(acc[8 + nb][0] * i2), elu1(acc[8 + nb][1] * i2));
        float2 v3 = make_float2(elu1(acc[8 + nb][2] * i3), elu1(acc[8 + nb][3] * i3));
        *(float2*)(o0 + col) = v0;
        *(float2*)(o1 + col) = v1;
        *(float2*)(o2 + col) = v2;
        *(float2*)(o3 + col) = v3;
    }
}

// ---------------- kernel 5: head-sum -> /H -> log_softmax -> mean ----------------
__global__ void final_kernel(float* __restrict__ out) {
    int warp = threadIdx.x >> 5;
    int lane = threadIdx.x & 31;
    int row = blockIdx.x * 8 + warp;               // 512 blocks -> 4096 rows
    float x0 = 0, x1 = 0, x2 = 0, x3 = 0;
    #pragma unroll
    for (int hh = 0; hh < HH; hh++) {
        float4 v = *(const float4*)(g_haccum + ((size_t)hh * NN + row) * DD + lane * 4);
        x0 += v.x; x1 += v.y; x2 += v.z; x3 += v.w;
    }
    x0 *= 0.125f; x1 *= 0.125f; x2 *= 0.125f; x3 *= 0.125f;
    float mx = fmaxf(fmaxf(x0, x1), fmaxf(x2, x3));
    #pragma unroll
    for (int o = 16; o; o >>= 1) mx = fmaxf(mx, __shfl_xor_sync(0xffffffffu, mx, o));
    float se = __expf(x0 - mx) + __expf(x1 - mx) + __expf(x2 - mx) + __expf(x3 - mx);
    float sx = x0 + x1 + x2 + x3;
    #pragma unroll
    for (int o = 16; o; o >>= 1) {
        se += __shfl_xor_sync(0xffffffffu, se, o);
        sx += __shfl_xor_sync(0xffffffffu, sx, o);
    }
    if (lane == 0) out[row] = sx * (1.0f / 128.0f) - mx - logf(se);
}

// ---------------- launch ----------------
extern "C" void kernel_launch(void* const* d_in, const int* in_sizes, int n_in,
                              void* d_out, int out_size) {
    const float* feature = (const float*)d_in[0];
    const int* adj = (const int*)d_in[1];
    const float* W = (const float*)d_in[2];
    const float* a1 = (const float*)d_in[3];
    const float* a2 = (const float*)d_in[4];
    float* out = (float*)d_out;

    static int attr_set = 0;
    if (!attr_set) {
        cudaFuncSetAttribute(attn_kernel, cudaFuncAttributeMaxDynamicSharedMemorySize,
                             ATTN_SMEM_BYTES);
        attr_set = 1;
    }

    prep_kernel<<<2048, 256>>>(feature, W);
    pack_adj_kernel<<<65536, 256>>>(adj);
    proj_kernel<<<dim3(32, 8), 256>>>(a1, a2);
    attn_kernel<<<dim3(16, 8), 640, ATTN_SMEM_BYTES>>>();
    final_kernel<<<512, 256>>>(out);
}

// round 12
// speedup vs baseline: 1.0638x; 1.0638x over previous
#include <cuda_runtime.h>
#include <cuda_bf16.h>
#include <cstdint>

#define NN 4096
#define FF 512
#define DD 128
#define HH 8
#define KC 64
#define NCHUNK (NN / KC)

// ---------------- scratch (static device globals; no allocs) ----------------
__device__ __nv_bfloat16 g_featb[NN * FF];          // 4 MB
__device__ __nv_bfloat16 g_Wb[HH * FF * DD];        // 1 MB
__device__ __nv_bfloat16 g_Whb[HH * NN * DD];       // 8 MB row-major [h][j][d]
__device__ float g_ratio[HH * NN];                  // exp(-0.8 s1)
__device__ float g_e2p[HH * NN];                    // exp(s2)
__device__ float g_e2n[HH * NN];                    // exp(0.2 s2)
__device__ unsigned g_adjbits[NN * (NN / 32)];      // 2 MB
__device__ float g_accum[NN * DD];                  // 2 MB head-summed elu(h')

// ---------------- helpers ----------------
__device__ __forceinline__ unsigned pack_bf16x2(float lo, float hi) {
    unsigned r;
    asm("cvt.rn.bf16x2.f32 %0, %1, %2;" : "=r"(r) : "f"(hi), "f"(lo));
    return r;
}
__device__ __forceinline__ unsigned smem_u32(const void* p) {
    return (unsigned)__cvta_generic_to_shared(p);
}
__device__ __forceinline__ unsigned SWZ(unsigned off) {        // SW128 swizzle
    return off ^ ((off >> 3) & 0x70);
}
__device__ __forceinline__ void ldsm_x4(unsigned addr, unsigned& r0, unsigned& r1,
                                        unsigned& r2, unsigned& r3) {
    asm volatile("ldmatrix.sync.aligned.m8n8.x4.shared.b16 {%0,%1,%2,%3}, [%4];"
                 : "=r"(r0), "=r"(r1), "=r"(r2), "=r"(r3) : "r"(addr));
}
__device__ __forceinline__ void ldsm_x4_t(unsigned addr, unsigned& r0, unsigned& r1,
                                          unsigned& r2, unsigned& r3) {
    asm volatile("ldmatrix.sync.aligned.m8n8.x4.trans.shared.b16 {%0,%1,%2,%3}, [%4];"
                 : "=r"(r0), "=r"(r1), "=r"(r2), "=r"(r3) : "r"(addr));
}
__device__ __forceinline__ void mma_bf16(float* c, unsigned a0, unsigned a1, unsigned a2,
                                         unsigned a3, unsigned b0, unsigned b1) {
    asm volatile(
        "mma.sync.aligned.m16n8k16.row.col.f32.bf16.bf16.f32 "
        "{%0,%1,%2,%3}, {%4,%5,%6,%7}, {%8,%9}, {%0,%1,%2,%3};"
        : "+f"(c[0]), "+f"(c[1]), "+f"(c[2]), "+f"(c[3])
        : "r"(a0), "r"(a1), "r"(a2), "r"(a3), "r"(b0), "r"(b1));
}
#define CP_ASYNC16(dst, src) \
    asm volatile("cp.async.cg.shared.global [%0], [%1], 16;" :: "r"(dst), "l"(src))
#define CP_COMMIT asm volatile("cp.async.commit_group;")
#define CP_WAIT1 asm volatile("cp.async.wait_group 1;")
#define CP_WAIT0 asm volatile("cp.async.wait_group 0;")

__device__ __forceinline__ void sts128(unsigned addr, unsigned a, unsigned b,
                                       unsigned c, unsigned d) {
    asm volatile("st.shared.v4.b32 [%0], {%1,%2,%3,%4};"
                 :: "r"(addr), "r"(a), "r"(b), "r"(c), "r"(d));
}
__device__ __forceinline__ void lds128f(float4& v, unsigned addr) {
    asm volatile("ld.shared.v4.f32 {%0,%1,%2,%3}, [%4];"
                 : "=f"(v.x), "=f"(v.y), "=f"(v.z), "=f"(v.w) : "r"(addr));
}
__device__ __forceinline__ float elu1(float v) {
    return (v > 0.0f) ? v : (__expf(v) - 1.0f);
}

// ---------------- kernel 1: fused prep (bf16 convert + zero accum) + adjacency pack ----
// blocks [0, 65536): pack 16.8M adjacency ints into bitmask (HBM-bound, 64 MB)
// blocks [65536, 67584): convert feature/W to bf16, zero g_accum (15 MB)
// Merging lets the two HBM streams pipeline across SMs instead of serializing.
__global__ void prep_pack_kernel(const float* __restrict__ feature,
                                 const float* __restrict__ W,
                                 const int* __restrict__ adj) {
    int b = blockIdx.x;
    if (b < 65536) {
        int gid = b * 256 + threadIdx.x;
        int w = gid >> 5;
        int lane = gid & 31;
        unsigned mask = __ballot_sync(0xffffffffu, adj[(size_t)w * 32 + lane] > 0);
        if (lane == 0) g_adjbits[w] = mask;
    } else {
        int i = (b - 65536) * 256 + threadIdx.x;      // 524288 threads
        #pragma unroll
        for (int r = 0; r < 4; r++) {
            int k = i + r * 524288;                    // NN*FF
            g_featb[k] = __float2bfloat16(feature[k]);
        }
        g_Wb[i] = __float2bfloat16(W[i]);             // HH*FF*DD
        g_accum[i] = 0.0f;                            // NN*DD
    }
}

// ---------------- kernel 2: Wh = feature @ W[h]; epilogue emits ratio/e2p/e2n ----------------
__global__ void __launch_bounds__(256, 2) proj_kernel(const float* __restrict__ a1,
                                                      const float* __restrict__ a2) {
    __shared__ __nv_bfloat16 sA[128][72];
    __shared__ __nv_bfloat16 sB[64][136];
    __shared__ float sA1[128], sA2[128];

    int h = blockIdx.y;
    int rowbase = blockIdx.x * 128;
    int t = threadIdx.x;
    int warp = t >> 5, lane = t & 31;
    int g = lane >> 2, tid4 = lane & 3;
    int m0 = warp * 16;
    int lr = (lane & 7) + ((lane & 8) ? 8 : 0);
    int lc = (lane & 16) ? 8 : 0;

    if (t < 128) sA1[t] = a1[h * DD + t];
    else sA2[t - 128] = a2[h * DD + (t - 128)];

    float acc[16][4];
    #pragma unroll
    for (int i = 0; i < 16; i++)
        #pragma unroll
        for (int j = 0; j < 4; j++) acc[i][j] = 0.0f;

    for (int kc = 0; kc < FF; kc += 64) {
        __syncthreads();
        const uint4* gA = (const uint4*)(g_featb + (size_t)rowbase * FF + kc);
        #pragma unroll
        for (int r = 0; r < 4; r++) {
            int li = r * 256 + t;
            int row = li >> 3, q = li & 7;
            *(uint4*)&sA[row][q * 8] = gA[row * (FF / 8) + q];
        }
        const uint4* gB = (const uint4*)(g_Wb + ((size_t)h * FF + kc) * DD);
        #pragma unroll
        for (int r = 0; r < 4; r++) {
            int li = r * 256 + t;
            int row = li >> 4, q = li & 15;
            *(uint4*)&sB[row][q * 8] = gB[row * 16 + q];
        }
        __syncthreads();

        #pragma unroll
        for (int kk = 0; kk < 64; kk += 16) {
            unsigned a0, a1r, a2r, a3;
            ldsm_x4(smem_u32(&sA[m0 + lr][kk + lc]), a0, a1r, a2r, a3);
            #pragma unroll
            for (int nb = 0; nb < 8; nb++) {
                unsigned b0, b1, b2, b3;
                ldsm_x4_t(smem_u32(&sB[kk + lr][nb * 16 + lc]), b0, b1, b2, b3);
                mma_bf16(acc[2 * nb], a0, a1r, a2r, a3, b0, b1);
                mma_bf16(acc[2 * nb + 1], a0, a1r, a2r, a3, b2, b3);
            }
        }
    }

    int row_lo = rowbase + m0 + g;
    int row_hi = row_lo + 8;

    // write Wh (bf16, row-major [h][j][d])
    __nv_bfloat16* outlo = g_Whb + ((size_t)h * NN + row_lo) * DD;
    __nv_bfloat16* outhi = g_Whb + ((size_t)h * NN + row_hi) * DD;
    #pragma unroll
    for (int i = 0; i < 16; i++) {
        int col = i * 8 + 2 * tid4;
        *(unsigned*)(outlo + col) = pack_bf16x2(acc[i][0], acc[i][1]);
        *(unsigned*)(outhi + col) = pack_bf16x2(acc[i][2], acc[i][3]);
    }

    // fused s1/s2 dot products from fp32 accumulators
    float d1lo = 0, d2lo = 0, d1hi = 0, d2hi = 0;
    #pragma unroll
    for (int i = 0; i < 16; i++) {
        int col = i * 8 + 2 * tid4;
        float v1a = sA1[col], v1b = sA1[col + 1];
        float v2a = sA2[col], v2b = sA2[col + 1];
        d1lo += acc[i][0] * v1a + acc[i][1] * v1b;
        d1hi += acc[i][2] * v1a + acc[i][3] * v1b;
        d2lo += acc[i][0] * v2a + acc[i][1] * v2b;
        d2hi += acc[i][2] * v2a + acc[i][3] * v2b;
    }
    #pragma unroll
    for (int o = 1; o <= 2; o <<= 1) {
        d1lo += __shfl_xor_sync(0xffffffffu, d1lo, o);
        d1hi += __shfl_xor_sync(0xffffffffu, d1hi, o);
        d2lo += __shfl_xor_sync(0xffffffffu, d2lo, o);
        d2hi += __shfl_xor_sync(0xffffffffu, d2hi, o);
    }
    if (tid4 == 0) {
        int ilo = h * NN + row_lo, ihi = h * NN + row_hi;
        g_ratio[ilo] = __expf(-0.8f * d1lo); g_ratio[ihi] = __expf(-0.8f * d1hi);
        g_e2p[ilo] = __expf(d2lo);           g_e2p[ihi] = __expf(d2hi);
        g_e2n[ilo] = __expf(0.2f * d2lo);    g_e2n[ihi] = __expf(0.2f * d2hi);
    }
}

// ---------------- kernel 3: fused masked-softmax aggregation ----------------
// EXACT config that measured 145.9us (R6): fp32 e2p/e2n tables, single P buffer,
// 4Mx2N warps, ones-mma Z, 2 barriers/chunk. Only the epilogue changed:
// atomicAdd into 2MB g_accum (head sum) instead of 16MB per-head stores.
#define OFF_P    0
#define OFF_B    16384
#define OFF_E2P  49152
#define OFF_E2N  65536
#define ATTN_SMEM_BYTES (81920 + 1024)

__global__ void __launch_bounds__(256, 2) attn_kernel() {
    extern __shared__ char smraw[];
    unsigned sb = (smem_u32(smraw) + 1023u) & ~1023u;
    unsigned sP = sb + OFF_P;
    unsigned sBb = sb + OFF_B;                 // + buf*16384 + half*8192
    unsigned sE2P = sb + OFF_E2P, sE2N = sb + OFF_E2N;

    int t = threadIdx.x;
    int w = t >> 5, lane = t & 31;
    int g = lane >> 2, tid4 = lane & 3;
    int mw = w & 3, nw = w >> 2;
    int m0 = mw * 32;
    int n0 = nw * 64;
    int lr = (lane & 7) + ((lane & 8) ? 8 : 0);
    int lc = (lane & 16) ? 8 : 0;
    int h = blockIdx.y;
    int rowbase = blockIdx.x * 128;

    // score-gen mapping: thread -> (row, 32-col half)
    int prow = t >> 1;
    int phalf = t & 1;
    int srow = rowbase + prow;
    float ratio = g_ratio[h * NN + srow];

    // stage e2p/e2n (whole head, 16 KB each) + B tile 0, one cp.async group
    #pragma unroll
    for (int r = 0; r < 4; r++) {
        CP_ASYNC16(sE2P + (t + r * 256) * 16, g_e2p + (size_t)h * NN + (t + r * 256) * 4);
        CP_ASYNC16(sE2N + (t + r * 256) * 16, g_e2n + (size_t)h * NN + (t + r * 256) * 4);
    }
    {
        const __nv_bfloat16* src = g_Whb + (size_t)h * NN * DD;
        #pragma unroll
        for (int r = 0; r < 4; r++) {
            int li = r * 256 + t;
            int row = li >> 4, q = li & 15;
            CP_ASYNC16(sBb + (q >> 3) * 8192 + SWZ(row * 128 + (q & 7) * 16),
                       src + row * DD + q * 8);
        }
    }
    CP_COMMIT;
    CP_WAIT0;
    __syncthreads();

    float acc[16][4];
    #pragma unroll
    for (int i = 0; i < 16; i++)
        #pragma unroll
        for (int j = 0; j < 4; j++) acc[i][j] = 0.0f;
    float zA[4] = {0, 0, 0, 0}, zB[4] = {0, 0, 0, 0};
    const unsigned ONES = 0x3f803f80u;          // bf16 (1.0, 1.0)

    for (int i = 0; i < NCHUNK; i++) {
        int kc = i * KC;
        // prefetch B(i+1)
        if (i + 1 < NCHUNK) {
            const __nv_bfloat16* src = g_Whb + ((size_t)h * NN + kc + KC) * DD;
            unsigned dstb = sBb + ((i + 1) & 1) * 16384;
            #pragma unroll
            for (int r = 0; r < 4; r++) {
                int li = r * 256 + t;
                int row = li >> 4, q = li & 15;
                CP_ASYNC16(dstb + (q >> 3) * 8192 + SWZ(row * 128 + (q & 7) * 16),
                           src + row * DD + q * 8);
            }
        }
        CP_COMMIT;

        // score-gen: 32 q values for (srow, cols kc+phalf*32 .. +31) -> swizzled sP
        unsigned bw = g_adjbits[(size_t)srow * (NN / 32) + i * 2 + phalf];
        #pragma unroll
        for (int gi = 0; gi < 4; gi++) {
            int c = phalf * 32 + gi * 8;
            float4 ep0, ep1, en0, en1;
            lds128f(ep0, sE2P + (kc + c) * 4);
            lds128f(ep1, sE2P + (kc + c) * 4 + 16);
            lds128f(en0, sE2N + (kc + c) * 4);
            lds128f(en1, sE2N + (kc + c) * 4 + 16);
            unsigned mb = bw >> (gi * 8);
            float q0 = (mb & 1u)   ? fmaxf(ep0.x, ratio * en0.x) : 0.0f;
            float q1 = (mb & 2u)   ? fmaxf(ep0.y, ratio * en0.y) : 0.0f;
            float q2 = (mb & 4u)   ? fmaxf(ep0.z, ratio * en0.z) : 0.0f;
            float q3 = (mb & 8u)   ? fmaxf(ep0.w, ratio * en0.w) : 0.0f;
            float q4 = (mb & 16u)  ? fmaxf(ep1.x, ratio * en1.x) : 0.0f;
            float q5 = (mb & 32u)  ? fmaxf(ep1.y, ratio * en1.y) : 0.0f;
            float q6 = (mb & 64u)  ? fmaxf(ep1.z, ratio * en1.z) : 0.0f;
            float q7 = (mb & 128u) ? fmaxf(ep1.w, ratio * en1.w) : 0.0f;
            sts128(sP + SWZ(prow * 128 + c * 2),
                   pack_bf16x2(q0, q1), pack_bf16x2(q2, q3),
                   pack_bf16x2(q4, q5), pack_bf16x2(q6, q7));
        }

        CP_WAIT1;                 // B(i) resident; B(i+1) may be in flight
        __syncthreads();          // P(i) visible to all warps

        unsigned bhalf = sBb + (i & 1) * 16384 + nw * 8192;
        #pragma unroll
        for (int kk = 0; kk < 4; kk++) {
            unsigned A00, A01, A02, A03, A10, A11, A12, A13;
            ldsm_x4(sP + SWZ((m0 + lr) * 128 + (kk * 16 + lc) * 2), A00, A01, A02, A03);
            ldsm_x4(sP + SWZ((m0 + 16 + lr) * 128 + (kk * 16 + lc) * 2), A10, A11, A12, A13);
            #pragma unroll
            for (int nb4 = 0; nb4 < 4; nb4++) {
                unsigned b0, b1, b2, b3;
                ldsm_x4_t(bhalf + SWZ((kk * 16 + lr) * 128 + (nb4 * 16 + lc) * 2),
                          b0, b1, b2, b3);
                mma_bf16(acc[2 * nb4],     A00, A01, A02, A03, b0, b1);
                mma_bf16(acc[2 * nb4 + 1], A00, A01, A02, A03, b2, b3);
                mma_bf16(acc[8 + 2 * nb4],     A10, A11, A12, A13, b0, b1);
                mma_bf16(acc[8 + 2 * nb4 + 1], A10, A11, A12, A13, b2, b3);
            }
            mma_bf16(zA, A00, A01, A02, A03, ONES, ONES);   // Z rows m0+g, m0+g+8
            mma_bf16(zB, A10, A11, A12, A13, ONES, ONES);   // Z rows +16, +24
        }
        __syncthreads();          // P(i) consumed; safe to overwrite next iter
    }

    // normalize + ELU + head-sum via atomics into 2MB g_accum
    int r0 = rowbase + m0 + g;
    float i0 = 1.0f / zA[0];
    float i1 = 1.0f / zA[2];
    float i2 = 1.0f / zB[0];
    float i3 = 1.0f / zB[2];
    float* o0 = g_accum + (size_t)r0 * DD;
    float* o1 = o0 + 8 * DD;
    float* o2 = o0 + 16 * DD;
    float* o3 = o0 + 24 * DD;
    #pragma unroll
    for (int nb = 0; nb < 8; nb++) {
        int col = n0 + nb * 8 + 2 * tid4;
        atomicAdd(o0 + col,     elu1(acc[nb][0] * i0));
        atomicAdd(o0 + col + 1, elu1(acc[nb][1] * i0));
        atomicAdd(o1 + col,     elu1(acc[nb][2] * i1));
        atomicAdd(o1 + col + 1, elu1(acc[nb][3] * i1));
        atomicAdd(o2 + col,     elu1(acc[8 + nb][0] * i2));
        atomicAdd(o2 + col + 1, elu1(acc[8 + nb][1] * i2));
        atomicAdd(o3 + col,     elu1(acc[8 + nb][2] * i3));
        atomicAdd(o3 + col + 1, elu1(acc[8 + nb][3] * i3));
    }
}

// ---------------- kernel 4: /H -> log_softmax -> mean (2 MB read) ----------------
__global__ void final_kernel(float* __restrict__ out) {
    int warp = threadIdx.x >> 5;
    int lane = threadIdx.x & 31;
    int row = blockIdx.x * 8 + warp;               // 512 blocks -> 4096 rows
    float4 v = *(const float4*)(g_accum + (size_t)row * DD + lane * 4);
    float x0 = v.x * 0.125f, x1 = v.y * 0.125f;    // /H (head mean)
    float x2 = v.z * 0.125f, x3 = v.w * 0.125f;
    float mx = fmaxf(fmaxf(x0, x1), fmaxf(x2, x3));
    #pragma unroll
    for (int o = 16; o; o >>= 1) mx = fmaxf(mx, __shfl_xor_sync(0xffffffffu, mx, o));
    float se = __expf(x0 - mx) + __expf(x1 - mx) + __expf(x2 - mx) + __expf(x3 - mx);
    float sx = x0 + x1 + x2 + x3;
    #pragma unroll
    for (int o = 16; o; o >>= 1) {
        se += __shfl_xor_sync(0xffffffffu, se, o);
        sx += __shfl_xor_sync(0xffffffffu, sx, o);
    }
    if (lane == 0) out[row] = sx * (1.0f / 128.0f) - mx - logf(se);
}

// ---------------- launch ----------------
extern "C" void kernel_launch(void* const* d_in, const int* in_sizes, int n_in,
                              void* d_out, int out_size) {
    const float* feature = (const float*)d_in[0];
    const int* adj = (const int*)d_in[1];
    const float* W = (const float*)d_in[2];
    const float* a1 = (const float*)d_in[3];
    const float* a2 = (const float*)d_in[4];
    float* out = (float*)d_out;

    static int attr_set = 0;
    if (!attr_set) {
        cudaFuncSetAttribute(attn_kernel, cudaFuncAttributeMaxDynamicSharedMemorySize,
                             ATTN_SMEM_BYTES);
        attr_set = 1;
    }

    prep_pack_kernel<<<67584, 256>>>(feature, W, adj);
    proj_kernel<<<dim3(32, 8), 256>>>(a1, a2);
    attn_kernel<<<dim3(32, 8), 256, ATTN_SMEM_BYTES>>>();
    final_kernel<<<512, 256>>>(out);
}

// round 13
// speedup vs baseline: 1.1034x; 1.0372x over previous
#include <cuda_runtime.h>
#include <cuda_bf16.h>
#include <cstdint>

#define NN 4096
#define FF 512
#define DD 128
#define HH 8

// ---------------- scratch (static device globals; no allocs) ----------------
__device__ __nv_bfloat16 g_featb[NN * FF];          // 4 MB
__device__ __nv_bfloat16 g_Wb[HH * FF * DD];        // 1 MB
__device__ __nv_bfloat16 g_Whb[HH * NN * DD];       // 8 MB
__device__ float g_e1p[HH * NN];                    // exp(s1)
__device__ float g_e1n[HH * NN];                    // exp(0.2 s1)
__device__ float g_e2p[HH * NN];                    // exp(s2)
__device__ float g_e2n[HH * NN];                    // exp(0.2 s2)
__device__ unsigned g_adjbits[NN * (NN / 32)];      // 2 MB
__device__ float g_accum[NN * DD];                  // 2 MB (sum over heads of elu(h'))

// ---------------- helpers ----------------
__device__ __forceinline__ unsigned pack_bf16x2(float lo, float hi) {
    unsigned r;
    asm("cvt.rn.bf16x2.f32 %0, %1, %2;" : "=r"(r) : "f"(hi), "f"(lo));
    return r;
}
__device__ __forceinline__ unsigned smem_u32(const void* p) {
    return (unsigned)__cvta_generic_to_shared(p);
}
__device__ __forceinline__ void ldsm_x4(unsigned addr, unsigned& r0, unsigned& r1,
                                        unsigned& r2, unsigned& r3) {
    asm volatile("ldmatrix.sync.aligned.m8n8.x4.shared.b16 {%0,%1,%2,%3}, [%4];"
                 : "=r"(r0), "=r"(r1), "=r"(r2), "=r"(r3) : "r"(addr));
}
__device__ __forceinline__ void ldsm_x4_t(unsigned addr, unsigned& r0, unsigned& r1,
                                          unsigned& r2, unsigned& r3) {
    asm volatile("ldmatrix.sync.aligned.m8n8.x4.trans.shared.b16 {%0,%1,%2,%3}, [%4];"
                 : "=r"(r0), "=r"(r1), "=r"(r2), "=r"(r3) : "r"(addr));
}
__device__ __forceinline__ void mma_bf16(float* c, unsigned a0, unsigned a1, unsigned a2,
                                         unsigned a3, unsigned b0, unsigned b1) {
    asm volatile(
        "mma.sync.aligned.m16n8k16.row.col.f32.bf16.bf16.f32 "
        "{%0,%1,%2,%3}, {%4,%5,%6,%7}, {%8,%9}, {%0,%1,%2,%3};"
        : "+f"(c[0]), "+f"(c[1]), "+f"(c[2]), "+f"(c[3])
        : "r"(a0), "r"(a1), "r"(a2), "r"(a3), "r"(b0), "r"(b1));
}
#define CP_ASYNC16(dst, src) \
    asm volatile("cp.async.cg.shared.global [%0], [%1], 16;" :: "r"(dst), "l"(src))
#define CP_ASYNC4(dst, src) \
    asm volatile("cp.async.ca.shared.global [%0], [%1], 4;" :: "r"(dst), "l"(src))
#define CP_COMMIT asm volatile("cp.async.commit_group;")
#define CP_WAIT1 asm volatile("cp.async.wait_group 1;")
#define CP_WAIT0 asm volatile("cp.async.wait_group 0;")

// ---------------- kernel 1: convert feature/W to bf16, zero accum ----------------
__global__ void prep_kernel(const float* __restrict__ feature, const float* __restrict__ W) {
    int i = blockIdx.x * 256 + threadIdx.x;          // 2048 blocks -> 524288 threads
    #pragma unroll
    for (int r = 0; r < 4; r++) {
        int k = i + r * 524288;                       // 4 * 524288 = NN*FF
        g_featb[k] = __float2bfloat16(feature[k]);
    }
    g_Wb[i] = __float2bfloat16(W[i]);                // HH*FF*DD == 524288
    g_accum[i] = 0.0f;                               // NN*DD   == 524288
}

// ---------------- kernel 2: adjacency -> bitmask ----------------
__global__ void pack_adj_kernel(const int* __restrict__ adj) {
    int gid = blockIdx.x * 256 + threadIdx.x;        // 65536 blocks
    int w = gid >> 5;
    int lane = gid & 31;
    unsigned mask = __ballot_sync(0xffffffffu, adj[(size_t)w * 32 + lane] > 0);
    if (lane == 0) g_adjbits[w] = mask;
}

// ---------------- kernel 3: Wh = feature @ W[h]; epilogue makes exp(s1/s2) ----------------
// grid (32 row-tiles, 8 heads), 256 threads (8 warps x 16 rows), full D=128
__global__ void __launch_bounds__(256, 2) proj_kernel(const float* __restrict__ a1,
                                                      const float* __restrict__ a2) {
    __shared__ __nv_bfloat16 sA[128][72];   // 128 rows x 64 k, padded
    __shared__ __nv_bfloat16 sB[64][136];   // 64 k x 128 d, padded
    __shared__ float sA1[128], sA2[128];

    int h = blockIdx.y;
    int rowbase = blockIdx.x * 128;
    int t = threadIdx.x;
    int warp = t >> 5, lane = t & 31;
    int g = lane >> 2, tid4 = lane & 3;
    int m0 = warp * 16;
    int lr = (lane & 7) + ((lane & 8) ? 8 : 0);
    int lc = (lane & 16) ? 8 : 0;

    if (t < 128) sA1[t] = a1[h * DD + t];
    else sA2[t - 128] = a2[h * DD + (t - 128)];

    float acc[16][4];
    #pragma unroll
    for (int i = 0; i < 16; i++)
        #pragma unroll
        for (int j = 0; j < 4; j++) acc[i][j] = 0.0f;

    for (int kc = 0; kc < FF; kc += 64) {
        __syncthreads();
        const uint4* gA = (const uint4*)(g_featb + (size_t)rowbase * FF + kc);
        #pragma unroll
        for (int r = 0; r < 4; r++) {
            int li = r * 256 + t;                    // 1024 chunks: 128 rows x 8
            int row = li >> 3, q = li & 7;
            *(uint4*)&sA[row][q * 8] = gA[row * (FF / 8) + q];
        }
        const uint4* gB = (const uint4*)(g_Wb + ((size_t)h * FF + kc) * DD);
        #pragma unroll
        for (int r = 0; r < 4; r++) {
            int li = r * 256 + t;                    // 1024 chunks: 64 rows x 16
            int row = li >> 4, q = li & 15;
            *(uint4*)&sB[row][q * 8] = gB[row * 16 + q];
        }
        __syncthreads();

        #pragma unroll
        for (int kk = 0; kk < 64; kk += 16) {
            unsigned a0, a1r, a2r, a3;
            ldsm_x4(smem_u32(&sA[m0 + lr][kk + lc]), a0, a1r, a2r, a3);
            #pragma unroll
            for (int nb = 0; nb < 8; nb++) {
                unsigned b0, b1, b2, b3;
                ldsm_x4_t(smem_u32(&sB[kk + lr][nb * 16 + lc]), b0, b1, b2, b3);
                mma_bf16(acc[2 * nb], a0, a1r, a2r, a3, b0, b1);
                mma_bf16(acc[2 * nb + 1], a0, a1r, a2r, a3, b2, b3);
            }
        }
    }

    int row_lo = rowbase + m0 + g;
    int row_hi = row_lo + 8;

    // write Wh (bf16)
    __nv_bfloat16* outlo = g_Whb + ((size_t)h * NN + row_lo) * DD;
    __nv_bfloat16* outhi = g_Whb + ((size_t)h * NN + row_hi) * DD;
    #pragma unroll
    for (int i = 0; i < 16; i++) {
        int col = i * 8 + 2 * tid4;
        *(unsigned*)(outlo + col) = pack_bf16x2(acc[i][0], acc[i][1]);
        *(unsigned*)(outhi + col) = pack_bf16x2(acc[i][2], acc[i][3]);
    }

    // fused s1/s2 dot products from fp32 accumulators
    float d1lo = 0, d2lo = 0, d1hi = 0, d2hi = 0;
    #pragma unroll
    for (int i = 0; i < 16; i++) {
        int col = i * 8 + 2 * tid4;
        float v1a = sA1[col], v1b = sA1[col + 1];
        float v2a = sA2[col], v2b = sA2[col + 1];
        d1lo += acc[i][0] * v1a + acc[i][1] * v1b;
        d1hi += acc[i][2] * v1a + acc[i][3] * v1b;
        d2lo += acc[i][0] * v2a + acc[i][1] * v2b;
        d2hi += acc[i][2] * v2a + acc[i][3] * v2b;
    }
    #pragma unroll
    for (int o = 1; o <= 2; o <<= 1) {
        d1lo += __shfl_xor_sync(0xffffffffu, d1lo, o);
        d1hi += __shfl_xor_sync(0xffffffffu, d1hi, o);
        d2lo += __shfl_xor_sync(0xffffffffu, d2lo, o);
        d2hi += __shfl_xor_sync(0xffffffffu, d2hi, o);
    }
    if (tid4 == 0) {
        int ilo = h * NN + row_lo, ihi = h * NN + row_hi;
        g_e1p[ilo] = __expf(d1lo);        g_e1p[ihi] = __expf(d1hi);
        g_e1n[ilo] = __expf(0.2f * d1lo); g_e1n[ihi] = __expf(0.2f * d1hi);
        g_e2p[ilo] = __expf(d2lo);        g_e2p[ihi] = __expf(d2hi);
        g_e2n[ilo] = __expf(0.2f * d2lo); g_e2n[ihi] = __expf(0.2f * d2hi);
    }
}

// ---------------- kernel 4: fused masked-softmax aggregation ----------------
// p_ij = max(E1p_i*E2p_j, E1n_i*E2n_j) masked; Z folded; no MUFU in hot loop.
// grid (32 row-tiles, 8 heads), 256 threads (8 warps x 16 rows), D=128.
__global__ void __launch_bounds__(256, 2) attn_kernel() {
    __shared__ __nv_bfloat16 sB[2][64][136];   // double-buffered Wh tile
    __shared__ float sE2p[2][64], sE2n[2][64];

    int h = blockIdx.y;
    int rowbase = blockIdx.x * 128;
    int t = threadIdx.x;
    int warp = t >> 5, lane = t & 31;
    int g = lane >> 2, tid4 = lane & 3;
    int m0 = warp * 16;
    int lr = (lane & 7) + ((lane & 8) ? 8 : 0);
    int lc = (lane & 16) ? 8 : 0;

    int row_lo = rowbase + m0 + g;
    int row_hi = row_lo + 8;
    float e1p_lo = g_e1p[h * NN + row_lo];
    float e1p_hi = g_e1p[h * NN + row_hi];
    float e1n_lo = g_e1n[h * NN + row_lo];
    float e1n_hi = g_e1n[h * NN + row_hi];
    const uint2* bits_lo = (const uint2*)&g_adjbits[(size_t)row_lo * (NN / 32)];
    const uint2* bits_hi = (const uint2*)&g_adjbits[(size_t)row_hi * (NN / 32)];

    float acc[16][4];
    #pragma unroll
    for (int i = 0; i < 16; i++)
        #pragma unroll
        for (int j = 0; j < 4; j++) acc[i][j] = 0.0f;
    float z_lo = 0.0f, z_hi = 0.0f;

    // ---- prefetch tile 0 ----
    {
        const __nv_bfloat16* src = g_Whb + (size_t)h * NN * DD;
        #pragma unroll
        for (int r = 0; r < 4; r++) {
            int li = r * 256 + t;
            int row = li >> 4, q = li & 15;
            CP_ASYNC16(smem_u32(&sB[0][row][q * 8]), src + row * DD + q * 8);
        }
        if (t < 64) CP_ASYNC4(smem_u32(&sE2p[0][t]), &g_e2p[h * NN + t]);
        else if (t < 128) CP_ASYNC4(smem_u32(&sE2n[0][t - 64]), &g_e2n[h * NN + (t - 64)]);
    }
    CP_COMMIT;
    uint2 wl_cur = bits_lo[0];
    uint2 wh_cur = bits_hi[0];

    for (int it = 0; it < NN / 64; it++) {
        int nxt = it + 1;
        uint2 wl_nxt = make_uint2(0, 0), wh_nxt = make_uint2(0, 0);
        if (nxt < NN / 64) {
            int kc = nxt * 64;
            const __nv_bfloat16* src = g_Whb + ((size_t)h * NN + kc) * DD;
            int b = nxt & 1;
            #pragma unroll
            for (int r = 0; r < 4; r++) {
                int li = r * 256 + t;
                int row = li >> 4, q = li & 15;
                CP_ASYNC16(smem_u32(&sB[b][row][q * 8]), src + row * DD + q * 8);
            }
            if (t < 64) CP_ASYNC4(smem_u32(&sE2p[b][t]), &g_e2p[h * NN + kc + t]);
            else if (t < 128) CP_ASYNC4(smem_u32(&sE2n[b][t - 64]), &g_e2n[h * NN + kc + (t - 64)]);
            wl_nxt = bits_lo[nxt];
            wh_nxt = bits_hi[nxt];
        }
        CP_COMMIT;
        if (nxt < NN / 64) { CP_WAIT1; } else { CP_WAIT0; }
        __syncthreads();

        int b = it & 1;
        unsigned long long BL = (unsigned long long)wl_cur.x | ((unsigned long long)wl_cur.y << 32);
        unsigned long long BH = (unsigned long long)wh_cur.x | ((unsigned long long)wh_cur.y << 32);

        #pragma unroll
        for (int kk = 0; kk < 64; kk += 16) {
            int c0 = kk + 2 * tid4;
            float2 ep_a = *(const float2*)&sE2p[b][c0];
            float2 ep_b = *(const float2*)&sE2p[b][c0 + 8];
            float2 en_a = *(const float2*)&sE2n[b][c0];
            float2 en_b = *(const float2*)&sE2n[b][c0 + 8];

            float p00 = fmaxf(e1p_lo * ep_a.x, e1n_lo * en_a.x);
            float p01 = fmaxf(e1p_lo * ep_a.y, e1n_lo * en_a.y);
            float p02 = fmaxf(e1p_lo * ep_b.x, e1n_lo * en_b.x);
            float p03 = fmaxf(e1p_lo * ep_b.y, e1n_lo * en_b.y);
            float p10 = fmaxf(e1p_hi * ep_a.x, e1n_hi * en_a.x);
            float p11 = fmaxf(e1p_hi * ep_a.y, e1n_hi * en_a.y);
            float p12 = fmaxf(e1p_hi * ep_b.x, e1n_hi * en_b.x);
            float p13 = fmaxf(e1p_hi * ep_b.y, e1n_hi * en_b.y);

            unsigned ml = (unsigned)(BL >> c0);
            unsigned mh = (unsigned)(BH >> c0);
            p00 = (ml & 1u)   ? p00 : 0.0f;
            p01 = (ml & 2u)   ? p01 : 0.0f;
            p02 = (ml & 256u) ? p02 : 0.0f;
            p03 = (ml & 512u) ? p03 : 0.0f;
            p10 = (mh & 1u)   ? p10 : 0.0f;
            p11 = (mh & 2u)   ? p11 : 0.0f;
            p12 = (mh & 256u) ? p12 : 0.0f;
            p13 = (mh & 512u) ? p13 : 0.0f;

            z_lo += (p00 + p01) + (p02 + p03);
            z_hi += (p10 + p11) + (p12 + p13);

            unsigned a0 = pack_bf16x2(p00, p01);
            unsigned a1 = pack_bf16x2(p10, p11);
            unsigned a2 = pack_bf16x2(p02, p03);
            unsigned a3 = pack_bf16x2(p12, p13);

            #pragma unroll
            for (int nb = 0; nb < 8; nb++) {
                unsigned b0, b1, b2, b3;
                ldsm_x4_t(smem_u32(&sB[b][kk + lr][nb * 16 + lc]), b0, b1, b2, b3);
                mma_bf16(acc[2 * nb], a0, a1, a2, a3, b0, b1);
                mma_bf16(acc[2 * nb + 1], a0, a1, a2, a3, b2, b3);
            }
        }
        __syncthreads();
        wl_cur = wl_nxt;
        wh_cur = wh_nxt;
    }

    // quad-reduce Z (cols partitioned over tid4)
    z_lo += __shfl_xor_sync(0xffffffffu, z_lo, 1);
    z_lo += __shfl_xor_sync(0xffffffffu, z_lo, 2);
    z_hi += __shfl_xor_sync(0xffffffffu, z_hi, 1);
    z_hi += __shfl_xor_sync(0xffffffffu, z_hi, 2);
    float inv_lo = 1.0f / z_lo;
    float inv_hi = 1.0f / z_hi;

    float* out_lo = g_accum + (size_t)row_lo * DD;
    float* out_hi = g_accum + (size_t)row_hi * DD;
    #pragma unroll
    for (int i = 0; i < 16; i++) {
        int col = i * 8 + 2 * tid4;
        float v0 = acc[i][0] * inv_lo;
        float v1 = acc[i][1] * inv_lo;
        float v2 = acc[i][2] * inv_hi;
        float v3 = acc[i][3] * inv_hi;
        v0 = (v0 > 0.0f) ? v0 : (__expf(v0) - 1.0f);   // elu
        v1 = (v1 > 0.0f) ? v1 : (__expf(v1) - 1.0f);
        v2 = (v2 > 0.0f) ? v2 : (__expf(v2) - 1.0f);
        v3 = (v3 > 0.0f) ? v3 : (__expf(v3) - 1.0f);
        atomicAdd(out_lo + col, v0);
        atomicAdd(out_lo + col + 1, v1);
        atomicAdd(out_hi + col, v2);
        atomicAdd(out_hi + col + 1, v3);
    }
}

// ---------------- kernel 5: head-mean -> log_softmax -> mean ----------------
__global__ void final_kernel(float* __restrict__ out) {
    int warp = threadIdx.x >> 5;
    int lane = threadIdx.x & 31;
    int row = blockIdx.x * 8 + warp;               // 512 blocks -> 4096 rows
    float4 v = *(const float4*)(g_accum + (size_t)row * DD + lane * 4);
    float x0 = v.x * 0.125f, x1 = v.y * 0.125f;    // /H (head mean)
    float x2 = v.z * 0.125f, x3 = v.w * 0.125f;
    float mx = fmaxf(fmaxf(x0, x1), fmaxf(x2, x3));
    #pragma unroll
    for (int o = 16; o; o >>= 1) mx = fmaxf(mx, __shfl_xor_sync(0xffffffffu, mx, o));
    float se = __expf(x0 - mx) + __expf(x1 - mx) + __expf(x2 - mx) + __expf(x3 - mx);
    float sx = x0 + x1 + x2 + x3;
    #pragma unroll
    for (int o = 16; o; o >>= 1) {
        se += __shfl_xor_sync(0xffffffffu, se, o);
        sx += __shfl_xor_sync(0xffffffffu, sx, o);
    }
    if (lane == 0) out[row] = sx * (1.0f / 128.0f) - mx - logf(se);
}

// ---------------- launch (fork-join: pack_adj overlaps prep+proj) ----------------
extern "C" void kernel_launch(void* const* d_in, const int* in_sizes, int n_in,
                              void* d_out, int out_size) {
    const float* feature = (const float*)d_in[0];
    const int* adj = (const int*)d_in[1];
    const float* W = (const float*)d_in[2];
    const float* a1 = (const float*)d_in[3];
    const float* a2 = (const float*)d_in[4];
    float* out = (float*)d_out;

    static cudaStream_t s_pack = nullptr;
    static cudaEvent_t ev_fork = nullptr, ev_join = nullptr;
    if (!s_pack) {   // created on the (uncaptured) correctness call
        cudaStreamCreateWithFlags(&s_pack, cudaStreamNonBlocking);
        cudaEventCreateWithFlags(&ev_fork, cudaEventDisableTiming);
        cudaEventCreateWithFlags(&ev_join, cudaEventDisableTiming);
    }

    // fork: pack_adj (HBM-bound, independent) runs concurrently with prep+proj
    cudaEventRecord(ev_fork, 0);
    cudaStreamWaitEvent(s_pack, ev_fork, 0);
    pack_adj_kernel<<<65536, 256, 0, s_pack>>>(adj);
    cudaEventRecord(ev_join, s_pack);

    prep_kernel<<<2048, 256>>>(feature, W);
    proj_kernel<<<dim3(32, 8), 256>>>(a1, a2);

    // join: attn needs g_adjbits
    cudaStreamWaitEvent(0, ev_join, 0);
    attn_kernel<<<dim3(32, 8), 256>>>();
    final_kernel<<<512, 256>>>(out);
}

// round 14
// speedup vs baseline: 1.1131x; 1.0088x over previous
#include <cuda_runtime.h>
#include <cuda_bf16.h>
#include <cstdint>

#define NN 4096
#define FF 512
#define DD 128
#define HH 8

// ---------------- scratch (static device globals; no allocs) ----------------
__device__ __nv_bfloat16 g_featb[NN * FF];          // 4 MB
__device__ __nv_bfloat16 g_Wb[HH * FF * DD];        // 1 MB
__device__ __nv_bfloat16 g_Whb[HH * NN * DD];       // 8 MB
__device__ float g_e1p[HH * NN];                    // exp(s1)
__device__ float g_e1n[HH * NN];                    // exp(0.2 s1)
__device__ float g_e2p[HH * NN];                    // exp(s2)
__device__ float g_e2n[HH * NN];                    // exp(0.2 s2)
__device__ unsigned g_adjbits[NN * (NN / 32)];      // 2 MB
__device__ float g_accum[NN * DD];                  // 2 MB (sum over heads of elu(h'))

// ---------------- helpers ----------------
__device__ __forceinline__ unsigned pack_bf16x2(float lo, float hi) {
    unsigned r;
    asm("cvt.rn.bf16x2.f32 %0, %1, %2;" : "=r"(r) : "f"(hi), "f"(lo));
    return r;
}
__device__ __forceinline__ unsigned smem_u32(const void* p) {
    return (unsigned)__cvta_generic_to_shared(p);
}
__device__ __forceinline__ void ldsm_x4(unsigned addr, unsigned& r0, unsigned& r1,
                                        unsigned& r2, unsigned& r3) {
    asm volatile("ldmatrix.sync.aligned.m8n8.x4.shared.b16 {%0,%1,%2,%3}, [%4];"
                 : "=r"(r0), "=r"(r1), "=r"(r2), "=r"(r3) : "r"(addr));
}
__device__ __forceinline__ void ldsm_x4_t(unsigned addr, unsigned& r0, unsigned& r1,
                                          unsigned& r2, unsigned& r3) {
    asm volatile("ldmatrix.sync.aligned.m8n8.x4.trans.shared.b16 {%0,%1,%2,%3}, [%4];"
                 : "=r"(r0), "=r"(r1), "=r"(r2), "=r"(r3) : "r"(addr));
}
__device__ __forceinline__ void mma_bf16(float* c, unsigned a0, unsigned a1, unsigned a2,
                                         unsigned a3, unsigned b0, unsigned b1) {
    asm volatile(
        "mma.sync.aligned.m16n8k16.row.col.f32.bf16.bf16.f32 "
        "{%0,%1,%2,%3}, {%4,%5,%6,%7}, {%8,%9}, {%0,%1,%2,%3};"
        : "+f"(c[0]), "+f"(c[1]), "+f"(c[2]), "+f"(c[3])
        : "r"(a0), "r"(a1), "r"(a2), "r"(a3), "r"(b0), "r"(b1));
}
#define CP_ASYNC16(dst, src) \
    asm volatile("cp.async.cg.shared.global [%0], [%1], 16;" :: "r"(dst), "l"(src))
#define CP_ASYNC4(dst, src) \
    asm volatile("cp.async.ca.shared.global [%0], [%1], 4;" :: "r"(dst), "l"(src))
#define CP_COMMIT asm volatile("cp.async.commit_group;")
#define CP_WAIT1 asm volatile("cp.async.wait_group 1;")
#define CP_WAIT0 asm volatile("cp.async.wait_group 0;")

// ---------------- kernel 1: convert feature/W to bf16, zero accum ----------------
__global__ void prep_kernel(const float* __restrict__ feature, const float* __restrict__ W) {
    int i = blockIdx.x * 256 + threadIdx.x;          // 2048 blocks -> 524288 threads
    #pragma unroll
    for (int r = 0; r < 4; r++) {
        int k = i + r * 524288;                       // 4 * 524288 = NN*FF
        g_featb[k] = __float2bfloat16(feature[k]);
    }
    g_Wb[i] = __float2bfloat16(W[i]);                // HH*FF*DD == 524288
    g_accum[i] = 0.0f;                               // NN*DD   == 524288
}

// ---------------- kernel 2: adjacency -> bitmask ----------------
__global__ void pack_adj_kernel(const int* __restrict__ adj) {
    int gid = blockIdx.x * 256 + threadIdx.x;        // 65536 blocks
    int w = gid >> 5;
    int lane = gid & 31;
    unsigned mask = __ballot_sync(0xffffffffu, adj[(size_t)w * 32 + lane] > 0);
    if (lane == 0) g_adjbits[w] = mask;
}

// ---------------- kernel 3: Wh = feature @ W[h]; cp.async double-buffered ----------------
// grid (32 row-tiles, 8 heads), 256 threads (8 warps x 16 rows), full D=128.
// A tile: 128x64 bf16 at 144B row stride (pad); B tile: 64x128 bf16 at 272B stride.
#define PSA_BUF 18432          // 128 * 144
#define PSB_BUF 17408          // 64 * 272
#define POFF_B  (2 * PSA_BUF)  // 36864
#define PROJ_SMEM_BYTES (POFF_B + 2 * PSB_BUF + 256)   // ~72 KB

__global__ void __launch_bounds__(256, 2) proj_kernel(const float* __restrict__ a1,
                                                      const float* __restrict__ a2) {
    extern __shared__ char psm[];
    unsigned sbase = (smem_u32(psm) + 127u) & ~127u;
    unsigned sA0 = sbase;                 // 2 x 18432
    unsigned sB0 = sbase + POFF_B;        // 2 x 17408
    __shared__ float sA1[128], sA2[128];

    int h = blockIdx.y;
    int rowbase = blockIdx.x * 128;
    int t = threadIdx.x;
    int warp = t >> 5, lane = t & 31;
    int g = lane >> 2, tid4 = lane & 3;
    int m0 = warp * 16;
    int lr = (lane & 7) + ((lane & 8) ? 8 : 0);
    int lc = (lane & 16) ? 8 : 0;

    if (t < 128) sA1[t] = a1[h * DD + t];
    else sA2[t - 128] = a2[h * DD + (t - 128)];

    float acc[16][4];
    #pragma unroll
    for (int i = 0; i < 16; i++)
        #pragma unroll
        for (int j = 0; j < 4; j++) acc[i][j] = 0.0f;

    // --- issue chunk 0 ---
    {
        #pragma unroll
        for (int r = 0; r < 4; r++) {
            int li = r * 256 + t;
            int row = li >> 3, q = li & 7;
            CP_ASYNC16(sA0 + row * 144 + q * 16,
                       g_featb + (size_t)(rowbase + row) * FF + q * 8);
        }
        #pragma unroll
        for (int r = 0; r < 4; r++) {
            int li = r * 256 + t;
            int row = li >> 4, q = li & 15;
            CP_ASYNC16(sB0 + row * 272 + q * 16,
                       g_Wb + ((size_t)h * FF + row) * DD + q * 8);
        }
    }
    CP_COMMIT;

    for (int c = 0; c < FF / 64; c++) {
        int kc = c * 64;
        // prefetch chunk c+1 into the other buffer
        if (c + 1 < FF / 64) {
            int nb_ = (c + 1) & 1;
            #pragma unroll
            for (int r = 0; r < 4; r++) {
                int li = r * 256 + t;
                int row = li >> 3, q = li & 7;
                CP_ASYNC16(sA0 + nb_ * PSA_BUF + row * 144 + q * 16,
                           g_featb + (size_t)(rowbase + row) * FF + kc + 64 + q * 8);
            }
            #pragma unroll
            for (int r = 0; r < 4; r++) {
                int li = r * 256 + t;
                int row = li >> 4, q = li & 15;
                CP_ASYNC16(sB0 + nb_ * PSB_BUF + row * 272 + q * 16,
                           g_Wb + ((size_t)h * FF + kc + 64 + row) * DD + q * 8);
            }
        }
        CP_COMMIT;
        if (c + 1 < FF / 64) { CP_WAIT1; } else { CP_WAIT0; }
        __syncthreads();

        int buf = c & 1;
        unsigned aBase = sA0 + buf * PSA_BUF;
        unsigned bBase = sB0 + buf * PSB_BUF;
        #pragma unroll
        for (int kk = 0; kk < 64; kk += 16) {
            unsigned a0, a1r, a2r, a3;
            ldsm_x4(aBase + (m0 + lr) * 144 + (kk + lc) * 2, a0, a1r, a2r, a3);
            #pragma unroll
            for (int nb = 0; nb < 8; nb++) {
                unsigned b0, b1, b2, b3;
                ldsm_x4_t(bBase + (kk + lr) * 272 + (nb * 16 + lc) * 2, b0, b1, b2, b3);
                mma_bf16(acc[2 * nb], a0, a1r, a2r, a3, b0, b1);
                mma_bf16(acc[2 * nb + 1], a0, a1r, a2r, a3, b2, b3);
            }
        }
        __syncthreads();
    }

    int row_lo = rowbase + m0 + g;
    int row_hi = row_lo + 8;

    // write Wh (bf16)
    __nv_bfloat16* outlo = g_Whb + ((size_t)h * NN + row_lo) * DD;
    __nv_bfloat16* outhi = g_Whb + ((size_t)h * NN + row_hi) * DD;
    #pragma unroll
    for (int i = 0; i < 16; i++) {
        int col = i * 8 + 2 * tid4;
        *(unsigned*)(outlo + col) = pack_bf16x2(acc[i][0], acc[i][1]);
        *(unsigned*)(outhi + col) = pack_bf16x2(acc[i][2], acc[i][3]);
    }

    // fused s1/s2 dot products from fp32 accumulators
    float d1lo = 0, d2lo = 0, d1hi = 0, d2hi = 0;
    #pragma unroll
    for (int i = 0; i < 16; i++) {
        int col = i * 8 + 2 * tid4;
        float v1a = sA1[col], v1b = sA1[col + 1];
        float v2a = sA2[col], v2b = sA2[col + 1];
        d1lo += acc[i][0] * v1a + acc[i][1] * v1b;
        d1hi += acc[i][2] * v1a + acc[i][3] * v1b;
        d2lo += acc[i][0] * v2a + acc[i][1] * v2b;
        d2hi += acc[i][2] * v2a + acc[i][3] * v2b;
    }
    #pragma unroll
    for (int o = 1; o <= 2; o <<= 1) {
        d1lo += __shfl_xor_sync(0xffffffffu, d1lo, o);
        d1hi += __shfl_xor_sync(0xffffffffu, d1hi, o);
        d2lo += __shfl_xor_sync(0xffffffffu, d2lo, o);
        d2hi += __shfl_xor_sync(0xffffffffu, d2hi, o);
    }
    if (tid4 == 0) {
        int ilo = h * NN + row_lo, ihi = h * NN + row_hi;
        g_e1p[ilo] = __expf(d1lo);        g_e1p[ihi] = __expf(d1hi);
        g_e1n[ilo] = __expf(0.2f * d1lo); g_e1n[ihi] = __expf(0.2f * d1hi);
        g_e2p[ilo] = __expf(d2lo);        g_e2p[ihi] = __expf(d2hi);
        g_e2n[ilo] = __expf(0.2f * d2lo); g_e2n[ihi] = __expf(0.2f * d2hi);
    }
}

// ---------------- kernel 4: fused masked-softmax aggregation ----------------
// p_ij = max(E1p_i*E2p_j, E1n_i*E2n_j) masked; Z folded; no MUFU in hot loop.
// grid (32 row-tiles, 8 heads), 256 threads (8 warps x 16 rows), D=128.
__global__ void __launch_bounds__(256, 2) attn_kernel() {
    __shared__ __nv_bfloat16 sB[2][64][136];   // double-buffered Wh tile
    __shared__ float sE2p[2][64], sE2n[2][64];

    int h = blockIdx.y;
    int rowbase = blockIdx.x * 128;
    int t = threadIdx.x;
    int warp = t >> 5, lane = t & 31;
    int g = lane >> 2, tid4 = lane & 3;
    int m0 = warp * 16;
    int lr = (lane & 7) + ((lane & 8) ? 8 : 0);
    int lc = (lane & 16) ? 8 : 0;

    int row_lo = rowbase + m0 + g;
    int row_hi = row_lo + 8;
    float e1p_lo = g_e1p[h * NN + row_lo];
    float e1p_hi = g_e1p[h * NN + row_hi];
    float e1n_lo = g_e1n[h * NN + row_lo];
    float e1n_hi = g_e1n[h * NN + row_hi];
    const uint2* bits_lo = (const uint2*)&g_adjbits[(size_t)row_lo * (NN / 32)];
    const uint2* bits_hi = (const uint2*)&g_adjbits[(size_t)row_hi * (NN / 32)];

    float acc[16][4];
    #pragma unroll
    for (int i = 0; i < 16; i++)
        #pragma unroll
        for (int j = 0; j < 4; j++) acc[i][j] = 0.0f;
    float z_lo = 0.0f, z_hi = 0.0f;

    // ---- prefetch tile 0 ----
    {
        const __nv_bfloat16* src = g_Whb + (size_t)h * NN * DD;
        #pragma unroll
        for (int r = 0; r < 4; r++) {
            int li = r * 256 + t;
            int row = li >> 4, q = li & 15;
            CP_ASYNC16(smem_u32(&sB[0][row][q * 8]), src + row * DD + q * 8);
        }
        if (t < 64) CP_ASYNC4(smem_u32(&sE2p[0][t]), &g_e2p[h * NN + t]);
        else if (t < 128) CP_ASYNC4(smem_u32(&sE2n[0][t - 64]), &g_e2n[h * NN + (t - 64)]);
    }
    CP_COMMIT;
    uint2 wl_cur = bits_lo[0];
    uint2 wh_cur = bits_hi[0];

    for (int it = 0; it < NN / 64; it++) {
        int nxt = it + 1;
        uint2 wl_nxt = make_uint2(0, 0), wh_nxt = make_uint2(0, 0);
        if (nxt < NN / 64) {
            int kc = nxt * 64;
            const __nv_bfloat16* src = g_Whb + ((size_t)h * NN + kc) * DD;
            int b = nxt & 1;
            #pragma unroll
            for (int r = 0; r < 4; r++) {
                int li = r * 256 + t;
                int row = li >> 4, q = li & 15;
                CP_ASYNC16(smem_u32(&sB[b][row][q * 8]), src + row * DD + q * 8);
            }
            if (t < 64) CP_ASYNC4(smem_u32(&sE2p[b][t]), &g_e2p[h * NN + kc + t]);
            else if (t < 128) CP_ASYNC4(smem_u32(&sE2n[b][t - 64]), &g_e2n[h * NN + kc + (t - 64)]);
            wl_nxt = bits_lo[nxt];
            wh_nxt = bits_hi[nxt];
        }
        CP_COMMIT;
        if (nxt < NN / 64) { CP_WAIT1; } else { CP_WAIT0; }
        __syncthreads();

        int b = it & 1;
        unsigned long long BL = (unsigned long long)wl_cur.x | ((unsigned long long)wl_cur.y << 32);
        unsigned long long BH = (unsigned long long)wh_cur.x | ((unsigned long long)wh_cur.y << 32);

        #pragma unroll
        for (int kk = 0; kk < 64; kk += 16) {
            int c0 = kk + 2 * tid4;
            float2 ep_a = *(const float2*)&sE2p[b][c0];
            float2 ep_b = *(const float2*)&sE2p[b][c0 + 8];
            float2 en_a = *(const float2*)&sE2n[b][c0];
            float2 en_b = *(const float2*)&sE2n[b][c0 + 8];

            float p00 = fmaxf(e1p_lo * ep_a.x, e1n_lo * en_a.x);
            float p01 = fmaxf(e1p_lo * ep_a.y, e1n_lo * en_a.y);
            float p02 = fmaxf(e1p_lo * ep_b.x, e1n_lo * en_b.x);
            float p03 = fmaxf(e1p_lo * ep_b.y, e1n_lo * en_b.y);
            float p10 = fmaxf(e1p_hi * ep_a.x, e1n_hi * en_a.x);
            float p11 = fmaxf(e1p_hi * ep_a.y, e1n_hi * en_a.y);
            float p12 = fmaxf(e1p_hi * ep_b.x, e1n_hi * en_b.x);
            float p13 = fmaxf(e1p_hi * ep_b.y, e1n_hi * en_b.y);

            unsigned ml = (unsigned)(BL >> c0);
            unsigned mh = (unsigned)(BH >> c0);
            p00 = (ml & 1u)   ? p00 : 0.0f;
            p01 = (ml & 2u)   ? p01 : 0.0f;
            p02 = (ml & 256u) ? p02 : 0.0f;
            p03 = (ml & 512u) ? p03 : 0.0f;
            p10 = (mh & 1u)   ? p10 : 0.0f;
            p11 = (mh & 2u)   ? p11 : 0.0f;
            p12 = (mh & 256u) ? p12 : 0.0f;
            p13 = (mh & 512u) ? p13 : 0.0f;

            z_lo += (p00 + p01) + (p02 + p03);
            z_hi += (p10 + p11) + (p12 + p13);

            unsigned a0 = pack_bf16x2(p00, p01);
            unsigned a1 = pack_bf16x2(p10, p11);
            unsigned a2 = pack_bf16x2(p02, p03);
            unsigned a3 = pack_bf16x2(p12, p13);

            #pragma unroll
            for (int nb = 0; nb < 8; nb++) {
                unsigned b0, b1, b2, b3;
                ldsm_x4_t(smem_u32(&sB[b][kk + lr][nb * 16 + lc]), b0, b1, b2, b3);
                mma_bf16(acc[2 * nb], a0, a1, a2, a3, b0, b1);
                mma_bf16(acc[2 * nb + 1], a0, a1, a2, a3, b2, b3);
            }
        }
        __syncthreads();
        wl_cur = wl_nxt;
        wh_cur = wh_nxt;
    }

    // quad-reduce Z (cols partitioned over tid4)
    z_lo += __shfl_xor_sync(0xffffffffu, z_lo, 1);
    z_lo += __shfl_xor_sync(0xffffffffu, z_lo, 2);
    z_hi += __shfl_xor_sync(0xffffffffu, z_hi, 1);
    z_hi += __shfl_xor_sync(0xffffffffu, z_hi, 2);
    float inv_lo = 1.0f / z_lo;
    float inv_hi = 1.0f / z_hi;

    float* out_lo = g_accum + (size_t)row_lo * DD;
    float* out_hi = g_accum + (size_t)row_hi * DD;
    #pragma unroll
    for (int i = 0; i < 16; i++) {
        int col = i * 8 + 2 * tid4;
        float v0 = acc[i][0] * inv_lo;
        float v1 = acc[i][1] * inv_lo;
        float v2 = acc[i][2] * inv_hi;
        float v3 = acc[i][3] * inv_hi;
        v0 = (v0 > 0.0f) ? v0 : (__expf(v0) - 1.0f);   // elu
        v1 = (v1 > 0.0f) ? v1 : (__expf(v1) - 1.0f);
        v2 = (v2 > 0.0f) ? v2 : (__expf(v2) - 1.0f);
        v3 = (v3 > 0.0f) ? v3 : (__expf(v3) - 1.0f);
        atomicAdd(out_lo + col, v0);
        atomicAdd(out_lo + col + 1, v1);
        atomicAdd(out_hi + col, v2);
        atomicAdd(out_hi + col + 1, v3);
    }
}

// ---------------- kernel 5: head-mean -> log_softmax -> mean ----------------
__global__ void final_kernel(float* __restrict__ out) {
    int warp = threadIdx.x >> 5;
    int lane = threadIdx.x & 31;
    int row = blockIdx.x * 8 + warp;               // 512 blocks -> 4096 rows
    float4 v = *(const float4*)(g_accum + (size_t)row * DD + lane * 4);
    float x0 = v.x * 0.125f, x1 = v.y * 0.125f;    // /H (head mean)
    float x2 = v.z * 0.125f, x3 = v.w * 0.125f;
    float mx = fmaxf(fmaxf(x0, x1), fmaxf(x2, x3));
    #pragma unroll
    for (int o = 16; o; o >>= 1) mx = fmaxf(mx, __shfl_xor_sync(0xffffffffu, mx, o));
    float se = __expf(x0 - mx) + __expf(x1 - mx) + __expf(x2 - mx) + __expf(x3 - mx);
    float sx = x0 + x1 + x2 + x3;
    #pragma unroll
    for (int o = 16; o; o >>= 1) {
        se += __shfl_xor_sync(0xffffffffu, se, o);
        sx += __shfl_xor_sync(0xffffffffu, sx, o);
    }
    if (lane == 0) out[row] = sx * (1.0f / 128.0f) - mx - logf(se);
}

// ---------------- launch (fork-join: pack_adj overlaps prep+proj) ----------------
extern "C" void kernel_launch(void* const* d_in, const int* in_sizes, int n_in,
                              void* d_out, int out_size) {
    const float* feature = (const float*)d_in[0];
    const int* adj = (const int*)d_in[1];
    const float* W = (const float*)d_in[2];
    const float* a1 = (const float*)d_in[3];
    const float* a2 = (const float*)d_in[4];
    float* out = (float*)d_out;

    static cudaStream_t s_pack = nullptr;
    static cudaEvent_t ev_fork = nullptr, ev_join = nullptr;
    if (!s_pack) {   // created on the (uncaptured) correctness call
        cudaStreamCreateWithFlags(&s_pack, cudaStreamNonBlocking);
        cudaEventCreateWithFlags(&ev_fork, cudaEventDisableTiming);
        cudaEventCreateWithFlags(&ev_join, cudaEventDisableTiming);
        cudaFuncSetAttribute(proj_kernel, cudaFuncAttributeMaxDynamicSharedMemorySize,
                             PROJ_SMEM_BYTES);
    }

    // fork: pack_adj (HBM-bound, independent) runs concurrently with prep+proj
    cudaEventRecord(ev_fork, 0);
    cudaStreamWaitEvent(s_pack, ev_fork, 0);
    pack_adj_kernel<<<65536, 256, 0, s_pack>>>(adj);
    cudaEventRecord(ev_join, s_pack);

    prep_kernel<<<2048, 256>>>(feature, W);
    proj_kernel<<<dim3(32, 8), 256, PROJ_SMEM_BYTES>>>(a1, a2);

    // join: attn needs g_adjbits
    cudaStreamWaitEvent(0, ev_join, 0);
    attn_kernel<<<dim3(32, 8), 256>>>();
    final_kernel<<<512, 256>>>(out);
}